// round 10
// baseline (speedup 1.0000x reference)
#include <cuda_runtime.h>
#include <cstdint>
#include <cstddef>

#define TSTEPS 1024
#define BSZ 128
#define DSZ 256
#define HSZ 512
#define CSZ 1000

// x-projections, layout [t][M=2048][b].  1 GB
__device__ float g_P[(size_t)TSTEPS * 4 * HSZ * BSZ];
// Double-buffered hidden state, layout [b][j], tf32-rounded values.
__device__ float g_h2[2][BSZ * HSZ];
// Pre-converted tf32 operands
__device__ unsigned g_Wt32[2048 * 256];                   // [g*512+j][d]
__device__ unsigned g_xt32[(size_t)TSTEPS * BSZ * DSZ];   // [t][b][d]
// Barrier state
__device__ unsigned g_bar_count;
__device__ unsigned g_bar_gen;
__device__ unsigned g_flags[128 * 8];

__device__ __forceinline__ float fast_sigmoid(float x) {
    return __fdividef(1.0f, 1.0f + __expf(-x));
}
__device__ __forceinline__ float fast_tanh(float x) {
    return __fdividef(2.0f, 1.0f + __expf(-2.0f * x)) - 1.0f;
}
__device__ __forceinline__ unsigned cvt_tf32(float f) {
    unsigned u;
    asm("cvt.rna.tf32.f32 %0, %1;" : "=r"(u) : "f"(f));
    return u;
}

__device__ __forceinline__ void grid_barrier(unsigned nb) {
    __syncthreads();
    if (threadIdx.x == 0) {
        __threadfence();
        unsigned gen = *(volatile unsigned*)&g_bar_gen;
        unsigned arrived = atomicAdd(&g_bar_count, 1u);
        if (arrived == nb - 1u) {
            atomicExch(&g_bar_count, 0u);
            __threadfence();
            atomicAdd(&g_bar_gen, 1u);
        } else {
            while (*(volatile unsigned*)&g_bar_gen == gen) { __nanosleep(32); }
        }
        __threadfence();
    }
    __syncthreads();
}

// publish own flag with release semantics (orders all prior CTA stores via bar)
__device__ __forceinline__ void publish_flag(int ct, unsigned gen) {
    asm volatile("st.release.gpu.u32 [%0], %1;"
                 :: "l"(&g_flags[ct * 8]), "r"(gen) : "memory");
}
// every warp: lanes 0..7 poll the 8 writer flags of super-chunk sc (group ng)
__device__ __forceinline__ void poll_chunk(int sc, int ng, unsigned need) {
    int lane = threadIdx.x & 31;
    if (lane < 8) {
        const unsigned* f = &g_flags[((sc * 8 + lane) * 4 + ng) * 8];
        unsigned v;
        while (true) {
            asm volatile("ld.acquire.gpu.u32 %0, [%1];" : "=r"(v) : "l"(f) : "memory");
            if (v >= need) break;
            __nanosleep(20);
        }
    }
    __syncwarp();
}

__device__ __forceinline__ void cp16(void* dst_smem, const void* src) {
    unsigned d = (unsigned)__cvta_generic_to_shared(dst_smem);
    asm volatile("cp.async.cg.shared.global [%0], [%1], 16;\n" :: "r"(d), "l"(src));
}

#define MMA_TF32(c0,c1,c2,c3, a0,a1,a2,a3, b0,b1) \
    asm("mma.sync.aligned.m16n8k8.row.col.f32.tf32.tf32.f32 " \
        "{%0,%1,%2,%3}, {%4,%5,%6,%7}, {%8,%9}, {%0,%1,%2,%3};" \
        : "+f"(c0), "+f"(c1), "+f"(c2), "+f"(c3) \
        : "r"(a0), "r"(a1), "r"(a2), "r"(a3), "r"(b0), "r"(b1))

// ---------------------------------------------------------------------------
// Prep: W -> tf32 [M=g*512+j][d]
// ---------------------------------------------------------------------------
__global__ __launch_bounds__(256) void k_prep_w(
    const float* __restrict__ W0, const float* __restrict__ W1,
    const float* __restrict__ W2, const float* __restrict__ W3)
{
    int M = blockIdx.x;
    int g = M >> 9, j = M & 511;
    const float* W = (g == 0) ? W0 : (g == 1) ? W1 : (g == 2) ? W2 : W3;
    int d = threadIdx.x;
    g_Wt32[(size_t)M * 256 + d] = cvt_tf32(W[(size_t)d * HSZ + j]);
}

// Prep: x -> tf32 [t][b][d]
__global__ __launch_bounds__(64) void k_prep_x(const float* __restrict__ x)
{
    int t = blockIdx.x, b = blockIdx.y;
    int d4 = threadIdx.x * 4;
    float4 v = *(const float4*)&x[((size_t)b * TSTEPS + t) * DSZ + d4];
    uint4 o;
    o.x = cvt_tf32(v.x); o.y = cvt_tf32(v.y);
    o.z = cvt_tf32(v.z); o.w = cvt_tf32(v.w);
    *(uint4*)&g_xt32[((size_t)t * BSZ + b) * DSZ + d4] = o;
}

// ---------------------------------------------------------------------------
// Phase 1: tf32-mma GEMM, A (weights) resident, 16 timesteps per CTA.
// grid (16 m-tiles, 64 t-groups), 256 threads.
// smem: sA[128][260] = 133120 B | sB 2 x [128][68] = 69632 B -> 202752 B
// ---------------------------------------------------------------------------
#define XP_TB 16
__global__ __launch_bounds__(256, 1) void k_xproj3()
{
    extern __shared__ unsigned smu[];
    unsigned* sA = smu;             // 128 x 260
    unsigned* sB = smu + 33280;     // 2 x 8704

    const int M0 = blockIdx.x * 128;
    const int t0 = blockIdx.y * XP_TB;
    const int tid = threadIdx.x;
    const int w = tid >> 5, lane = tid & 31;
    const int gp = lane >> 2, tg = lane & 3;

    const unsigned* Asrc = g_Wt32 + (size_t)M0 * 256;

    // stage A (resident), one group
#pragma unroll
    for (int i = 0; i < 32; ++i) {
        int linear = tid + i * 256;
        int row = linear >> 6, slot = (linear & 63) * 4;
        cp16(&sA[row * 260 + slot], &Asrc[row * 256 + slot]);
    }
    asm volatile("cp.async.commit_group;");

    // stage B chunk q=0
    {
        const unsigned* Bsrc = g_xt32 + (size_t)t0 * BSZ * DSZ;
#pragma unroll
        for (int i = 0; i < 8; ++i) {
            int linear = tid + i * 256;
            int row = linear >> 4, slot = (linear & 15) * 4;
            cp16(&sB[row * 68 + slot], &Bsrc[row * 256 + slot]);
        }
    }
    asm volatile("cp.async.commit_group;");

    float acc[16][4];
#pragma unroll
    for (int f = 0; f < 16; ++f)
#pragma unroll
        for (int q = 0; q < 4; ++q) acc[f][q] = 0.0f;

    const int rA = (w * 16 + gp) * 260, rB = (w * 16 + gp + 8) * 260;

    for (int q = 0; q < XP_TB * 4; ++q) {
        if (q < XP_TB * 4 - 1) {
            int qn = q + 1;
            int tl = qn >> 2, c = qn & 3;
            const unsigned* Bsrc = g_xt32 + (size_t)(t0 + tl) * BSZ * DSZ + c * 64;
            unsigned* dB = sB + (qn & 1) * 8704;
#pragma unroll
            for (int i = 0; i < 8; ++i) {
                int linear = tid + i * 256;
                int row = linear >> 4, slot = (linear & 15) * 4;
                cp16(&dB[row * 68 + slot], &Bsrc[row * 256 + slot]);
            }
            asm volatile("cp.async.commit_group;");
            asm volatile("cp.async.wait_group 1;");
        } else {
            asm volatile("cp.async.wait_group 0;");
        }
        __syncthreads();
        const unsigned* B = sB + (q & 1) * 8704;
        const int kofs = (q & 3) * 64;
#pragma unroll
        for (int ksl = 0; ksl < 8; ++ksl) {
            int k0 = ksl * 8 + tg;
            unsigned a0 = sA[rA + kofs + k0];
            unsigned a1 = sA[rB + kofs + k0];
            unsigned a2 = sA[rA + kofs + k0 + 4];
            unsigned a3 = sA[rB + kofs + k0 + 4];
#pragma unroll
            for (int f = 0; f < 16; ++f) {
                unsigned b0 = B[(f * 8 + gp) * 68 + k0];
                unsigned b1 = B[(f * 8 + gp) * 68 + k0 + 4];
                MMA_TF32(acc[f][0], acc[f][1], acc[f][2], acc[f][3],
                         a0, a1, a2, a3, b0, b1);
            }
        }
        __syncthreads();

        if ((q & 3) == 3) {
            int t = t0 + (q >> 2);
            const size_t rbase = ((size_t)t * 2048 + M0 + w * 16 + gp) * 128;
#pragma unroll
            for (int f = 0; f < 16; ++f) {
                *(float2*)&g_P[rbase + f * 8 + tg * 2] =
                    make_float2(acc[f][0], acc[f][1]);
                *(float2*)&g_P[rbase + (size_t)8 * 128 + f * 8 + tg * 2] =
                    make_float2(acc[f][2], acc[f][3]);
                acc[f][0] = acc[f][1] = acc[f][2] = acc[f][3] = 0.0f;
            }
        }
    }
}

// ---------------------------------------------------------------------------
// Phase 2: persistent tf32-mma scan, pipelined producer flags.
// 128 CTAs = 32 row-groups (mg) x 4 batch-groups (ng).
// K=512 split into 4 super-chunks of 128 j (8 writer CTAs each), double-buffered.
// SMEM: A 131072 B | h 2x32x132 = 33792 B | E 64x34 = 8704 B -> 173568 B
// ---------------------------------------------------------------------------
__global__ __launch_bounds__(256, 1) void k_rnn3(
    const float* __restrict__ Wgh, const float* __restrict__ Wih,
    const float* __restrict__ Wfh, const float* __restrict__ Woh,
    const float* __restrict__ bgp, const float* __restrict__ bip,
    const float* __restrict__ bfp, const float* __restrict__ bop)
{
    extern __shared__ float sm[];
    unsigned* sAu = (unsigned*)sm;          // 32768 u
    float* sh_h = sm + 32768;               // 2 x 32 x 132
    float* sh_E = sm + 32768 + 8448;        // 64 x 34

    const int ct = blockIdx.x;
    const int mg = ct >> 2, ng = ct & 3;
    const int j0 = mg * 16;
    const int nbase = ng * 32;
    const int tid = threadIdx.x;
    const int w = tid >> 5, lane = tid & 31;
    const int mt = w & 3, nh = w >> 2;
    const int gp = lane >> 2, tg = lane & 3;

    // build pre-swizzled tf32 A fragments (once)
    {
        const float* Wt[4] = {Wgh, Wih, Wfh, Woh};
        for (int idx = tid; idx < 32768; idx += 256) {
            int mtb = idx >> 13;
            int rem = idx & 8191;
            int ks = rem >> 7;
            int ln = (rem >> 2) & 31;
            int q = rem & 3;
            int gpp = ln >> 2, tgg = ln & 3;
            int rowl = mtb * 16 + gpp + ((q & 1) << 3);
            int k = ks * 8 + tgg + ((q >> 1) << 2);
            int gate = rowl & 3;
            int j = j0 + (rowl >> 2);
            sAu[idx] = cvt_tf32(Wt[gate][(size_t)k * HSZ + j]);
        }
    }

    const int mA = mt * 16 + gp, mB = mA + 8;
    const int gateA = mA & 3, gateB = mB & 3;
    const int jA = j0 + (mA >> 2), jB = j0 + (mB >> 2);
    const size_t rowA = (size_t)gateA * HSZ + jA;
    const size_t rowB = (size_t)gateB * HSZ + jB;
    const int cb = nbase + nh * 16 + tg * 2;

    const float* Bt0[4] = {bgp, bip, bfp, bop};
    const float biasA = Bt0[gateA][jA];
    const float biasB = Bt0[gateB][jB];

    const int e_jj = tid >> 4;
    const int e_b = (tid & 15) * 2;
    const int e_jglob = j0 + e_jj;
    const int e_bglob = nbase + e_b;

    for (int i = tid; i < 512; i += 256) g_h2[0][ct * 512 + i] = 0.0f;
    if (tid == 0) *(volatile unsigned*)&g_flags[ct * 8] = 0u;
    grid_barrier(gridDim.x);

    float cst0 = 0.0f, cst1 = 0.0f;

    float2 pf0a, pf0b, pf1a, pf1b;
    {
        const float* P0 = g_P;
        pf0a = *(const float2*)&P0[rowA * 128 + cb];
        pf0b = *(const float2*)&P0[rowB * 128 + cb];
        pf1a = *(const float2*)&P0[rowA * 128 + cb + 8];
        pf1b = *(const float2*)&P0[rowB * 128 + cb + 8];
    }

    const unsigned* Abase = sAu + (mt * 64) * 128 + lane * 4;
    const int nAo = (nh * 16 + gp) * 132;
    const int nBo = (nh * 16 + 8 + gp) * 132;

    for (int t = 0; t < TSTEPS; ++t) {
        const float* hb = g_h2[t & 1];
        float* hn = g_h2[(t + 1) & 1];

        // even chains init with P + bias; odd chains zero
        float ae0 = pf0a.x + biasA, ae1 = pf0a.y + biasA;
        float ae2 = pf0b.x + biasB, ae3 = pf0b.y + biasB;
        float ae4 = pf1a.x + biasA, ae5 = pf1a.y + biasA;
        float ae6 = pf1b.x + biasB, ae7 = pf1b.y + biasB;
        float ao0 = 0, ao1 = 0, ao2 = 0, ao3 = 0;
        float ao4 = 0, ao5 = 0, ao6 = 0, ao7 = 0;

        if (t + 1 < TSTEPS) {
            const float* Pn = g_P + (size_t)(t + 1) * 2048 * 128;
            pf0a = *(const float2*)&Pn[rowA * 128 + cb];
            pf0b = *(const float2*)&Pn[rowB * 128 + cb];
            pf1a = *(const float2*)&Pn[rowA * 128 + cb + 8];
            pf1b = *(const float2*)&Pn[rowB * 128 + cb + 8];
        }

        // stage super-chunk 0 (after its 8 writer flags are up)
        poll_chunk(0, ng, (unsigned)t);
        {
            const float* src = hb + (size_t)nbase * HSZ;
#pragma unroll
            for (int i = 0; i < 4; ++i) {
                int linear = tid + i * 256;
                int row = linear >> 5, col4 = (linear & 31) * 4;
                cp16(&sh_h[row * 132 + col4], &src[(size_t)row * HSZ + col4]);
            }
        }
        asm volatile("cp.async.commit_group;");

        for (int sc = 0; sc < 4; ++sc) {
            if (sc < 3) {
                poll_chunk(sc + 1, ng, (unsigned)t);
                float* dst = sh_h + ((sc + 1) & 1) * 4224;
                const float* src = hb + (size_t)nbase * HSZ + (sc + 1) * 128;
#pragma unroll
                for (int i = 0; i < 4; ++i) {
                    int linear = tid + i * 256;
                    int row = linear >> 5, col4 = (linear & 31) * 4;
                    cp16(&dst[row * 132 + col4], &src[(size_t)row * HSZ + col4]);
                }
                asm volatile("cp.async.commit_group;");
                asm volatile("cp.async.wait_group 1;");
            } else {
                asm volatile("cp.async.wait_group 0;");
            }
            __syncthreads();
            const unsigned* hu = (const unsigned*)(sh_h + (sc & 1) * 4224);
#pragma unroll
            for (int k2 = 0; k2 < 8; ++k2) {
                int ks = sc * 16 + k2 * 2;
                uint4 a0 = *(const uint4*)&Abase[ks * 128];
                uint4 a1 = *(const uint4*)&Abase[(ks + 1) * 128];
                int k0 = k2 * 16 + tg;
                int k1 = k0 + 8;
                unsigned b00 = hu[nAo + k0], b01 = hu[nAo + k0 + 4];
                MMA_TF32(ae0, ae1, ae2, ae3, a0.x, a0.y, a0.z, a0.w, b00, b01);
                unsigned b10 = hu[nBo + k0], b11 = hu[nBo + k0 + 4];
                MMA_TF32(ae4, ae5, ae6, ae7, a0.x, a0.y, a0.z, a0.w, b10, b11);
                unsigned d00 = hu[nAo + k1], d01 = hu[nAo + k1 + 4];
                MMA_TF32(ao0, ao1, ao2, ao3, a1.x, a1.y, a1.z, a1.w, d00, d01);
                unsigned d10 = hu[nBo + k1], d11 = hu[nBo + k1 + 4];
                MMA_TF32(ao4, ao5, ao6, ao7, a1.x, a1.y, a1.z, a1.w, d10, d11);
            }
            __syncthreads();
        }

        // exchange preacts
        {
            int col0 = nh * 16 + tg * 2;
            *(float2*)&sh_E[mA * 34 + col0]     = make_float2(ae0 + ao0, ae1 + ao1);
            *(float2*)&sh_E[mB * 34 + col0]     = make_float2(ae2 + ao2, ae3 + ao3);
            *(float2*)&sh_E[mA * 34 + col0 + 8] = make_float2(ae4 + ao4, ae5 + ao5);
            *(float2*)&sh_E[mB * 34 + col0 + 8] = make_float2(ae6 + ao6, ae7 + ao7);
        }
        __syncthreads();

        // epilogue: gates for (e_jj, e_b) and (e_jj, e_b+1)
        {
            const float* E0 = &sh_E[(e_jj * 4 + 0) * 34 + e_b];
            const float* E1 = &sh_E[(e_jj * 4 + 1) * 34 + e_b];
            const float* E2 = &sh_E[(e_jj * 4 + 2) * 34 + e_b];
            const float* E3 = &sh_E[(e_jj * 4 + 3) * 34 + e_b];
            float gv0 = fast_tanh(E0[0]),    gv1 = fast_tanh(E0[1]);
            float iv0 = fast_sigmoid(E1[0]), iv1 = fast_sigmoid(E1[1]);
            float fv0 = fast_sigmoid(E2[0]), fv1 = fast_sigmoid(E2[1]);
            float ov0 = fast_sigmoid(E3[0]), ov1 = fast_sigmoid(E3[1]);
            cst0 = gv0 * iv0 + cst0 * fv0;
            cst1 = gv1 * iv1 + cst1 * fv1;
            ((unsigned*)hn)[(size_t)e_bglob * HSZ + e_jglob] =
                cvt_tf32(fast_tanh(cst0) * ov0);
            ((unsigned*)hn)[(size_t)(e_bglob + 1) * HSZ + e_jglob] =
                cvt_tf32(fast_tanh(cst1) * ov1);
        }
        __syncthreads();
        if (tid == 0) publish_flag(ct, (unsigned)(t + 1));
    }
}

// ---------------------------------------------------------------------------
// Phase 3: out[b][c] = h_final[b] . Wph[:,c] + bp[c].
// ---------------------------------------------------------------------------
__global__ __launch_bounds__(256) void k_out(
    const float* __restrict__ Wp, const float* __restrict__ bp,
    float* __restrict__ out)
{
    __shared__ float sh[HSZ];
    int b = blockIdx.x;
    const float* h = g_h2[0] + (size_t)b * HSZ;
    for (int i = threadIdx.x; i < HSZ; i += 256) sh[i] = h[i];
    __syncthreads();
    for (int c = threadIdx.x; c < CSZ; c += 256) {
        float acc = 0.0f;
#pragma unroll 8
        for (int k = 0; k < HSZ; ++k)
            acc += sh[k] * Wp[(size_t)k * CSZ + c];
        out[b * CSZ + c] = acc + bp[c];
    }
}

// ---------------------------------------------------------------------------

extern "C" void kernel_launch(void* const* d_in, const int* in_sizes, int n_in,
                              void* d_out, int out_size) {
    const float* x   = (const float*)d_in[0];
    const float* Wgx = (const float*)d_in[1];
    const float* Wgh = (const float*)d_in[2];
    const float* bg  = (const float*)d_in[3];
    const float* Wix = (const float*)d_in[4];
    const float* Wih = (const float*)d_in[5];
    const float* bi  = (const float*)d_in[6];
    const float* Wfx = (const float*)d_in[7];
    const float* Wfh = (const float*)d_in[8];
    const float* bf  = (const float*)d_in[9];
    const float* Wox = (const float*)d_in[10];
    const float* Woh = (const float*)d_in[11];
    const float* bo  = (const float*)d_in[12];
    const float* Wph = (const float*)d_in[13];
    const float* bp  = (const float*)d_in[14];
    float* out = (float*)d_out;

    (void)in_sizes; (void)n_in; (void)out_size;

    const int smem_xp  = 202752;   // A 133120 + B 69632
    const int smem_rnn = 173568;   // A 131072 + h 33792 + E 8704
    cudaFuncSetAttribute(k_xproj3, cudaFuncAttributeMaxDynamicSharedMemorySize, smem_xp);
    cudaFuncSetAttribute(k_rnn3,   cudaFuncAttributeMaxDynamicSharedMemorySize, smem_rnn);

    k_prep_w<<<2048, 256>>>(Wgx, Wix, Wfx, Wox);
    k_prep_x<<<dim3(TSTEPS, BSZ), 64>>>(x);
    k_xproj3<<<dim3(16, TSTEPS / XP_TB), 256, smem_xp>>>();
    k_rnn3<<<128, 256, smem_rnn>>>(Wgh, Wih, Wfh, Woh, bg, bi, bf, bo);
    k_out<<<BSZ, 256>>>(Wph, bp, out);
}

// round 11
// speedup vs baseline: 1.3267x; 1.3267x over previous
#include <cuda_runtime.h>
#include <cstdint>
#include <cstddef>

#define TSTEPS 1024
#define BSZ 128
#define DSZ 256
#define HSZ 512
#define CSZ 1000
#define HPAD 516   // padded h row stride (floats): %32 banks = 4 -> conflict-free, row 2064B %16 = 0

// x-projections, layout [t][M=2048][b].  1 GB
__device__ float g_P[(size_t)TSTEPS * 4 * HSZ * BSZ];
// Double-buffered hidden state, layout [b][HPAD], tf32-rounded values.
__device__ float g_h2[2][BSZ * HPAD];
// Pre-converted tf32 operands
__device__ unsigned g_Wt32[2048 * 256];                   // [g*512+j][d]
__device__ unsigned g_xt32[(size_t)TSTEPS * BSZ * DSZ];   // [t][b][d]
// Barrier state
__device__ unsigned g_bar_count;
__device__ unsigned g_bar_gen;
__device__ unsigned g_flags[128 * 8];

__device__ __forceinline__ float fast_sigmoid(float x) {
    return __fdividef(1.0f, 1.0f + __expf(-x));
}
__device__ __forceinline__ float fast_tanh(float x) {
    return __fdividef(2.0f, 1.0f + __expf(-2.0f * x)) - 1.0f;
}
__device__ __forceinline__ unsigned cvt_tf32(float f) {
    unsigned u;
    asm("cvt.rna.tf32.f32 %0, %1;" : "=r"(u) : "f"(f));
    return u;
}

__device__ __forceinline__ void grid_barrier(unsigned nb) {
    __syncthreads();
    if (threadIdx.x == 0) {
        __threadfence();
        unsigned gen = *(volatile unsigned*)&g_bar_gen;
        unsigned arrived = atomicAdd(&g_bar_count, 1u);
        if (arrived == nb - 1u) {
            atomicExch(&g_bar_count, 0u);
            __threadfence();
            atomicAdd(&g_bar_gen, 1u);
        } else {
            while (*(volatile unsigned*)&g_bar_gen == gen) { __nanosleep(32); }
        }
        __threadfence();
    }
    __syncthreads();
}

__device__ __forceinline__ void publish_flag(int ct, unsigned gen) {
    asm volatile("st.release.gpu.u32 [%0], %1;"
                 :: "l"(&g_flags[ct * 8]), "r"(gen) : "memory");
}

__device__ __forceinline__ void cp16(void* dst_smem, const void* src) {
    unsigned d = (unsigned)__cvta_generic_to_shared(dst_smem);
    asm volatile("cp.async.cg.shared.global [%0], [%1], 16;\n" :: "r"(d), "l"(src));
}

// ---- mbarrier + TMA bulk helpers ----
__device__ __forceinline__ void mbar_init(unsigned mbar, unsigned count) {
    asm volatile("mbarrier.init.shared.b64 [%0], %1;" :: "r"(mbar), "r"(count) : "memory");
}
__device__ __forceinline__ void mbar_expect_tx(unsigned mbar, unsigned bytes) {
    asm volatile("mbarrier.arrive.expect_tx.shared.b64 _, [%0], %1;"
                 :: "r"(mbar), "r"(bytes) : "memory");
}
__device__ __forceinline__ void mbar_wait(unsigned mbar, unsigned parity) {
    asm volatile(
        "{\n\t"
        ".reg .pred P;\n\t"
        "LAB_%=:\n\t"
        "mbarrier.try_wait.parity.shared.b64 P, [%0], %1, 0x989680;\n\t"
        "@P bra DONE_%=;\n\t"
        "bra LAB_%=;\n\t"
        "DONE_%=:\n\t"
        "}"
        :: "r"(mbar), "r"(parity) : "memory");
}
__device__ __forceinline__ void bulk_g2s(unsigned dst_smem, const void* src,
                                         unsigned bytes, unsigned mbar) {
    asm volatile(
        "cp.async.bulk.shared::cluster.global.mbarrier::complete_tx::bytes "
        "[%0], [%1], %2, [%3];"
        :: "r"(dst_smem), "l"(src), "r"(bytes), "r"(mbar) : "memory");
}

#define MMA_TF32(c0,c1,c2,c3, a0,a1,a2,a3, b0,b1) \
    asm("mma.sync.aligned.m16n8k8.row.col.f32.tf32.tf32.f32 " \
        "{%0,%1,%2,%3}, {%4,%5,%6,%7}, {%8,%9}, {%0,%1,%2,%3};" \
        : "+f"(c0), "+f"(c1), "+f"(c2), "+f"(c3) \
        : "r"(a0), "r"(a1), "r"(a2), "r"(a3), "r"(b0), "r"(b1))

// ---------------------------------------------------------------------------
// Prep: W -> tf32 [M=g*512+j][d]
// ---------------------------------------------------------------------------
__global__ __launch_bounds__(256) void k_prep_w(
    const float* __restrict__ W0, const float* __restrict__ W1,
    const float* __restrict__ W2, const float* __restrict__ W3)
{
    int M = blockIdx.x;
    int g = M >> 9, j = M & 511;
    const float* W = (g == 0) ? W0 : (g == 1) ? W1 : (g == 2) ? W2 : W3;
    int d = threadIdx.x;
    g_Wt32[(size_t)M * 256 + d] = cvt_tf32(W[(size_t)d * HSZ + j]);
}

// Prep: x -> tf32 [t][b][d]
__global__ __launch_bounds__(64) void k_prep_x(const float* __restrict__ x)
{
    int t = blockIdx.x, b = blockIdx.y;
    int d4 = threadIdx.x * 4;
    float4 v = *(const float4*)&x[((size_t)b * TSTEPS + t) * DSZ + d4];
    uint4 o;
    o.x = cvt_tf32(v.x); o.y = cvt_tf32(v.y);
    o.z = cvt_tf32(v.z); o.w = cvt_tf32(v.w);
    *(uint4*)&g_xt32[((size_t)t * BSZ + b) * DSZ + d4] = o;
}

// ---------------------------------------------------------------------------
// Phase 1: tf32-mma GEMM (proven R6 version). P[t][M][b] = W[M][:] . x[t][b][:]
// grid (16 m-tiles, 1024 t), 256 threads. Tile M=128, N=128, K=256 (4 chunks).
// ---------------------------------------------------------------------------
__global__ __launch_bounds__(256, 1) void k_xproj2()
{
    extern __shared__ unsigned smu[];
    unsigned* sA = smu;            // 2 x 8704
    unsigned* sB = smu + 17408;    // 2 x 8704

    const int M0 = blockIdx.x * 128;
    const int t  = blockIdx.y;
    const int tid = threadIdx.x;
    const int w = tid >> 5, lane = tid & 31;
    const int gp = lane >> 2, tg = lane & 3;

    float acc[16][4];
#pragma unroll
    for (int f = 0; f < 16; ++f)
#pragma unroll
        for (int q = 0; q < 4; ++q) acc[f][q] = 0.0f;

    const unsigned* Asrc = g_Wt32 + (size_t)M0 * 256;
    const unsigned* Bsrc = g_xt32 + (size_t)t * BSZ * DSZ;

#pragma unroll
    for (int i = 0; i < 8; ++i) {
        int linear = tid + i * 256;
        int row = linear >> 4, seg = (linear & 15) * 4;
        cp16(&sA[row * 68 + seg], &Asrc[row * 256 + seg]);
        cp16(&sB[row * 68 + seg], &Bsrc[row * 256 + seg]);
    }
    asm volatile("cp.async.commit_group;");

    for (int c = 0; c < 4; ++c) {
        if (c < 3) {
            int kc = (c + 1) * 64;
            unsigned* dA = sA + ((c + 1) & 1) * 8704;
            unsigned* dB = sB + ((c + 1) & 1) * 8704;
#pragma unroll
            for (int i = 0; i < 8; ++i) {
                int linear = tid + i * 256;
                int row = linear >> 4, seg = (linear & 15) * 4;
                cp16(&dA[row * 68 + seg], &Asrc[row * 256 + kc + seg]);
                cp16(&dB[row * 68 + seg], &Bsrc[row * 256 + kc + seg]);
            }
            asm volatile("cp.async.commit_group;");
            asm volatile("cp.async.wait_group 1;");
        } else {
            asm volatile("cp.async.wait_group 0;");
        }
        __syncthreads();
        const unsigned* A = sA + (c & 1) * 8704;
        const unsigned* B = sB + (c & 1) * 8704;
        const int rA = (w * 16 + gp) * 68, rB = (w * 16 + gp + 8) * 68;
#pragma unroll
        for (int ksl = 0; ksl < 8; ++ksl) {
            int k0 = ksl * 8 + tg;
            unsigned a0 = A[rA + k0];
            unsigned a1 = A[rB + k0];
            unsigned a2 = A[rA + k0 + 4];
            unsigned a3 = A[rB + k0 + 4];
#pragma unroll
            for (int f = 0; f < 16; ++f) {
                unsigned b0 = B[(f * 8 + gp) * 68 + k0];
                unsigned b1 = B[(f * 8 + gp) * 68 + k0 + 4];
                MMA_TF32(acc[f][0], acc[f][1], acc[f][2], acc[f][3],
                         a0, a1, a2, a3, b0, b1);
            }
        }
        __syncthreads();
    }

    const size_t rbase = ((size_t)t * 2048 + M0 + w * 16 + gp) * 128;
#pragma unroll
    for (int f = 0; f < 16; ++f) {
        *(float2*)&g_P[rbase + f * 8 + tg * 2] =
            make_float2(acc[f][0], acc[f][1]);
        *(float2*)&g_P[rbase + (size_t)8 * 128 + f * 8 + tg * 2] =
            make_float2(acc[f][2], acc[f][3]);
    }
}

// ---------------------------------------------------------------------------
// Phase 2: persistent tf32-mma scan with TMA-bulk h staging.
// 128 CTAs = 32 row-groups (mg) x 4 batch-groups (ng).
// CTA: 64 preact rows (16 j x 4 gates) x 32 batches; K = 512 in one resident pass.
// h staged per step by ONE cp.async.bulk of 66048 B (32 padded rows).
// SMEM: A 131072 B | h 32x516x4 = 66048 B | E 64x34x4 = 8704 B -> 205824 B
// ---------------------------------------------------------------------------
__global__ __launch_bounds__(256, 1) void k_rnn4(
    const float* __restrict__ Wgh, const float* __restrict__ Wih,
    const float* __restrict__ Wfh, const float* __restrict__ Woh,
    const float* __restrict__ bgp, const float* __restrict__ bip,
    const float* __restrict__ bfp, const float* __restrict__ bop)
{
    extern __shared__ float sm[];
    unsigned* sAu = (unsigned*)sm;          // 32768 u
    float* sh_h = sm + 32768;               // 32 x 516
    float* sh_E = sm + 32768 + 32 * HPAD;   // 64 x 34
    __shared__ __align__(8) unsigned long long mbar_store;
    const unsigned mbar = (unsigned)__cvta_generic_to_shared(&mbar_store);

    const int ct = blockIdx.x;
    const int mg = ct >> 2, ng = ct & 3;
    const int j0 = mg * 16;
    const int nbase = ng * 32;
    const int tid = threadIdx.x;
    const int w = tid >> 5, lane = tid & 31;
    const int mt = w & 3, nh = w >> 2;
    const int gp = lane >> 2, tg = lane & 3;

    // build pre-swizzled tf32 A fragments (once)
    {
        const float* Wt[4] = {Wgh, Wih, Wfh, Woh};
        for (int idx = tid; idx < 32768; idx += 256) {
            int mtb = idx >> 13;
            int rem = idx & 8191;
            int ks = rem >> 7;
            int ln = (rem >> 2) & 31;
            int q = rem & 3;
            int gpp = ln >> 2, tgg = ln & 3;
            int rowl = mtb * 16 + gpp + ((q & 1) << 3);
            int k = ks * 8 + tgg + ((q >> 1) << 2);
            int gate = rowl & 3;
            int j = j0 + (rowl >> 2);
            sAu[idx] = cvt_tf32(Wt[gate][(size_t)k * HSZ + j]);
        }
    }

    const int mA = mt * 16 + gp, mB = mA + 8;
    const int gateA = mA & 3, gateB = mB & 3;
    const int jA = j0 + (mA >> 2), jB = j0 + (mB >> 2);
    const size_t rowA = (size_t)gateA * HSZ + jA;
    const size_t rowB = (size_t)gateB * HSZ + jB;
    const int cb = nbase + nh * 16 + tg * 2;

    const float* Bt0[4] = {bgp, bip, bfp, bop};
    const float biasA = Bt0[gateA][jA];
    const float biasB = Bt0[gateB][jB];

    const int e_jj = tid >> 4;
    const int e_b = (tid & 15) * 2;
    const int e_jglob = j0 + e_jj;
    const int e_bglob = nbase + e_b;

    // init: zero h[0] (incl. padding), reset own flag, init mbarrier
    for (int i = tid; i < HPAD; i += 256) g_h2[0][(size_t)ct * HPAD + i] = 0.0f;
    if (tid == 0) {
        *(volatile unsigned*)&g_flags[ct * 8] = 0u;
        mbar_init(mbar, 1u);
    }
    grid_barrier(gridDim.x);

    float cst0 = 0.0f, cst1 = 0.0f;

    float2 pf0a, pf0b, pf1a, pf1b;
    {
        const float* P0 = g_P;
        pf0a = *(const float2*)&P0[rowA * 128 + cb];
        pf0b = *(const float2*)&P0[rowB * 128 + cb];
        pf1a = *(const float2*)&P0[rowA * 128 + cb + 8];
        pf1b = *(const float2*)&P0[rowB * 128 + cb + 8];
    }

    const unsigned* Abase = sAu + (mt * 64) * 128 + lane * 4;
    const int nAo = (nh * 16 + gp) * HPAD;
    const int nBo = (nh * 16 + 8 + gp) * HPAD;
    const unsigned sh_h_u32 = (unsigned)__cvta_generic_to_shared(sh_h);

    for (int t = 0; t < TSTEPS; ++t) {
        const float* hb = g_h2[t & 1];
        float* hn = g_h2[(t + 1) & 1];

        float ae0 = pf0a.x + biasA, ae1 = pf0a.y + biasA;
        float ae2 = pf0b.x + biasB, ae3 = pf0b.y + biasB;
        float ae4 = pf1a.x + biasA, ae5 = pf1a.y + biasA;
        float ae6 = pf1b.x + biasB, ae7 = pf1b.y + biasB;
        float ao0 = 0, ao1 = 0, ao2 = 0, ao3 = 0;
        float ao4 = 0, ao5 = 0, ao6 = 0, ao7 = 0;

        if (t + 1 < TSTEPS) {
            const float* Pn = g_P + (size_t)(t + 1) * 2048 * 128;
            pf0a = *(const float2*)&Pn[rowA * 128 + cb];
            pf0b = *(const float2*)&Pn[rowB * 128 + cb];
            pf1a = *(const float2*)&Pn[rowA * 128 + cb + 8];
            pf1b = *(const float2*)&Pn[rowB * 128 + cb + 8];
        }

        // warp 0: wait for all 32 group writers to publish h(t), then issue bulk
        if (w == 0) {
            const unsigned* f = &g_flags[(lane * 4 + ng) * 8];
            unsigned v;
            while (true) {
                asm volatile("ld.acquire.gpu.u32 %0, [%1];" : "=r"(v) : "l"(f) : "memory");
                if (v >= (unsigned)t) break;
                __nanosleep(20);
            }
            __syncwarp();
            if (lane == 0) {
                mbar_expect_tx(mbar, 32u * HPAD * 4u);
                bulk_g2s(sh_h_u32, hb + (size_t)nbase * HPAD, 32u * HPAD * 4u, mbar);
            }
        }
        // all threads wait for the TMA deposit
        mbar_wait(mbar, (unsigned)(t & 1));

        const unsigned* hu = (const unsigned*)sh_h;
#pragma unroll 8
        for (int k2 = 0; k2 < 32; ++k2) {
            uint4 a0 = *(const uint4*)&Abase[(k2 * 2) * 128];
            uint4 a1 = *(const uint4*)&Abase[(k2 * 2 + 1) * 128];
            int k0 = k2 * 16 + tg;
            int k1 = k0 + 8;
            unsigned b00 = hu[nAo + k0], b01 = hu[nAo + k0 + 4];
            MMA_TF32(ae0, ae1, ae2, ae3, a0.x, a0.y, a0.z, a0.w, b00, b01);
            unsigned b10 = hu[nBo + k0], b11 = hu[nBo + k0 + 4];
            MMA_TF32(ae4, ae5, ae6, ae7, a0.x, a0.y, a0.z, a0.w, b10, b11);
            unsigned d00 = hu[nAo + k1], d01 = hu[nAo + k1 + 4];
            MMA_TF32(ao0, ao1, ao2, ao3, a1.x, a1.y, a1.z, a1.w, d00, d01);
            unsigned d10 = hu[nBo + k1], d11 = hu[nBo + k1 + 4];
            MMA_TF32(ao4, ao5, ao6, ao7, a1.x, a1.y, a1.z, a1.w, d10, d11);
        }

        // exchange preacts
        {
            int col0 = nh * 16 + tg * 2;
            *(float2*)&sh_E[mA * 34 + col0]     = make_float2(ae0 + ao0, ae1 + ao1);
            *(float2*)&sh_E[mB * 34 + col0]     = make_float2(ae2 + ao2, ae3 + ao3);
            *(float2*)&sh_E[mA * 34 + col0 + 8] = make_float2(ae4 + ao4, ae5 + ao5);
            *(float2*)&sh_E[mB * 34 + col0 + 8] = make_float2(ae6 + ao6, ae7 + ao7);
        }
        __syncthreads();

        // epilogue: gates for (e_jj, e_b) and (e_jj, e_b+1)
        {
            const float* E0 = &sh_E[(e_jj * 4 + 0) * 34 + e_b];
            const float* E1 = &sh_E[(e_jj * 4 + 1) * 34 + e_b];
            const float* E2 = &sh_E[(e_jj * 4 + 2) * 34 + e_b];
            const float* E3 = &sh_E[(e_jj * 4 + 3) * 34 + e_b];
            float gv0 = fast_tanh(E0[0]),    gv1 = fast_tanh(E0[1]);
            float iv0 = fast_sigmoid(E1[0]), iv1 = fast_sigmoid(E1[1]);
            float fv0 = fast_sigmoid(E2[0]), fv1 = fast_sigmoid(E2[1]);
            float ov0 = fast_sigmoid(E3[0]), ov1 = fast_sigmoid(E3[1]);
            cst0 = gv0 * iv0 + cst0 * fv0;
            cst1 = gv1 * iv1 + cst1 * fv1;
            ((unsigned*)hn)[(size_t)e_bglob * HPAD + e_jglob] =
                cvt_tf32(fast_tanh(cst0) * ov0);
            ((unsigned*)hn)[(size_t)(e_bglob + 1) * HPAD + e_jglob] =
                cvt_tf32(fast_tanh(cst1) * ov1);
        }
        __syncthreads();
        if (tid == 0) publish_flag(ct, (unsigned)(t + 1));
    }
}

// ---------------------------------------------------------------------------
// Phase 3: out[b][c] = h_final[b] . Wph[:,c] + bp[c].
// ---------------------------------------------------------------------------
__global__ __launch_bounds__(256) void k_out(
    const float* __restrict__ Wp, const float* __restrict__ bp,
    float* __restrict__ out)
{
    __shared__ float sh[HSZ];
    int b = blockIdx.x;
    const float* h = g_h2[0] + (size_t)b * HPAD;   // t=1023 writes buffer (1024&1)=0
    for (int i = threadIdx.x; i < HSZ; i += 256) sh[i] = h[i];
    __syncthreads();
    for (int c = threadIdx.x; c < CSZ; c += 256) {
        float acc = 0.0f;
#pragma unroll 8
        for (int k = 0; k < HSZ; ++k)
            acc += sh[k] * Wp[(size_t)k * CSZ + c];
        out[b * CSZ + c] = acc + bp[c];
    }
}

// ---------------------------------------------------------------------------

extern "C" void kernel_launch(void* const* d_in, const int* in_sizes, int n_in,
                              void* d_out, int out_size) {
    const float* x   = (const float*)d_in[0];
    const float* Wgx = (const float*)d_in[1];
    const float* Wgh = (const float*)d_in[2];
    const float* bg  = (const float*)d_in[3];
    const float* Wix = (const float*)d_in[4];
    const float* Wih = (const float*)d_in[5];
    const float* bi  = (const float*)d_in[6];
    const float* Wfx = (const float*)d_in[7];
    const float* Wfh = (const float*)d_in[8];
    const float* bf  = (const float*)d_in[9];
    const float* Wox = (const float*)d_in[10];
    const float* Woh = (const float*)d_in[11];
    const float* bo  = (const float*)d_in[12];
    const float* Wph = (const float*)d_in[13];
    const float* bp  = (const float*)d_in[14];
    float* out = (float*)d_out;

    (void)in_sizes; (void)n_in; (void)out_size;

    const int smem_xp  = 34816 * 4;                              // 139264 B
    const int smem_rnn = (32768 + 32 * HPAD + 64 * 34) * 4;      // 205824 B
    cudaFuncSetAttribute(k_xproj2, cudaFuncAttributeMaxDynamicSharedMemorySize, smem_xp);
    cudaFuncSetAttribute(k_rnn4,   cudaFuncAttributeMaxDynamicSharedMemorySize, smem_rnn);

    k_prep_w<<<2048, 256>>>(Wgx, Wix, Wfx, Wox);
    k_prep_x<<<dim3(TSTEPS, BSZ), 64>>>(x);
    k_xproj2<<<dim3(16, TSTEPS), 256, smem_xp>>>();
    k_rnn4<<<128, 256, smem_rnn>>>(Wgh, Wih, Wfh, Woh, bg, bi, bf, bo);
    k_out<<<BSZ, 256>>>(Wph, bp, out);
}